// round 10
// baseline (speedup 1.0000x reference)
#include <cuda_runtime.h>
#include <cuda_fp16.h>
#include <cstdint>

#define N_IN   200000
#define N_OUT  400000
#define K3     27
#define MP     100000
#define C      128
#define EPS    1e-5f

#define TILE_M 128
#define NTHR   256
#define NTILES 782                           // ceil(MP/128)
#define TASKS  (K3 * NTILES)                 // 21114
#define TPB    72
#define GRID_MAIN ((TASKS + TPB - 1) / TPB)  // 294

// ---------------------------------------------------------------------------
// persistent device scratch (allocations are forbidden)
// ---------------------------------------------------------------------------
__device__ float g_sum[C];
__device__ float g_sumsq[C];

__device__ __half g_fh[(size_t)N_IN * C];      // feats, fp16
__device__ __half g_wt[(size_t)K3 * C * C];    // W^T: [k][n(c_out)][c_in], fp16

// ---------------------------------------------------------------------------
// helpers
// ---------------------------------------------------------------------------
__device__ __forceinline__ uint32_t smem_u32(const void* p) {
    uint32_t a;
    asm("{ .reg .u64 t; cvta.to.shared.u64 t, %1; cvt.u32.u64 %0, t; }"
        : "=r"(a) : "l"(p));
    return a;
}
__device__ __forceinline__ void red_v4(float* p, float a, float b, float c, float d) {
    asm volatile("red.global.add.v4.f32 [%0], {%1, %2, %3, %4};"
                 :: "l"(p), "f"(a), "f"(b), "f"(c), "f"(d) : "memory");
}
__device__ __forceinline__ void ldsm_x4(uint32_t& r0, uint32_t& r1,
                                        uint32_t& r2, uint32_t& r3, uint32_t addr) {
    asm volatile("ldmatrix.sync.aligned.m8n8.x4.shared.b16 {%0,%1,%2,%3}, [%4];"
                 : "=r"(r0), "=r"(r1), "=r"(r2), "=r"(r3) : "r"(addr));
}
__device__ __forceinline__ void mma16816(float* c, uint32_t a0, uint32_t a1,
                                         uint32_t a2, uint32_t a3,
                                         uint32_t b0, uint32_t b1) {
    asm volatile(
        "mma.sync.aligned.m16n8k16.row.col.f32.f16.f16.f32 "
        "{%0,%1,%2,%3}, {%4,%5,%6,%7}, {%8,%9}, {%0,%1,%2,%3};"
        : "+f"(c[0]), "+f"(c[1]), "+f"(c[2]), "+f"(c[3])
        : "r"(a0), "r"(a1), "r"(a2), "r"(a3), "r"(b0), "r"(b1));
}
__device__ __forceinline__ void cp16(uint32_t dst, const void* src) {
    asm volatile("cp.async.cg.shared.global [%0], [%1], 16;"
                 :: "r"(dst), "l"(src) : "memory");
}
__device__ __forceinline__ void cp16z(uint32_t dst, const void* src, int nbytes) {
    asm volatile("cp.async.ca.shared.global [%0], [%1], 16, %2;"
                 :: "r"(dst), "l"(src), "r"(nbytes) : "memory");
}
#define CP_COMMIT()  asm volatile("cp.async.commit_group;" ::: "memory")
#define CP_WAIT(N)   asm volatile("cp.async.wait_group %0;" :: "n"(N) : "memory")

__device__ __forceinline__ void sts_v2(uint32_t addr, float a, float b) {
    asm volatile("st.shared.v2.f32 [%0], {%1, %2};" :: "r"(addr), "f"(a), "f"(b));
}
__device__ __forceinline__ float4 lds_v4(uint32_t addr) {
    float4 v;
    asm volatile("ld.shared.v4.f32 {%0,%1,%2,%3}, [%4];"
                 : "=f"(v.x), "=f"(v.y), "=f"(v.z), "=f"(v.w) : "r"(addr));
    return v;
}

// ---------------------------------------------------------------------------
// kernel 1: fused prep — zero output+stats, feats->fp16, W transpose->fp16
// (R6 version — fused beats split by ~14us)
// ---------------------------------------------------------------------------
__global__ void prep_kernel(float* __restrict__ out,
                            const float* __restrict__ feats,
                            const float* __restrict__ W) {
    const size_t stride = (size_t)gridDim.x * blockDim.x;
    const size_t base = (size_t)blockIdx.x * blockDim.x + threadIdx.x;

    float4 z = make_float4(0.f, 0.f, 0.f, 0.f);
    for (size_t i = base; i < (size_t)N_OUT * (C / 4); i += stride)
        ((float4*)out)[i] = z;

    for (size_t i = base; i < (size_t)N_IN * (C / 4); i += stride) {
        float4 v = ((const float4*)feats)[i];
        __half h[4];
        h[0] = __float2half_rn(v.x);
        h[1] = __float2half_rn(v.y);
        h[2] = __float2half_rn(v.z);
        h[3] = __float2half_rn(v.w);
        ((uint2*)g_fh)[i] = *(uint2*)h;
    }

    for (size_t i = base; i < (size_t)K3 * C * C; i += stride) {
        int c  = (int)(i & (C - 1));
        int nn = (int)((i >> 7) & (C - 1));
        int k  = (int)(i >> 14);
        g_wt[i] = __float2half_rn(W[(size_t)k * C * C + (size_t)c * C + nn]);
    }

    if (blockIdx.x == 0 && threadIdx.x < C) {
        g_sum[threadIdx.x]   = 0.f;
        g_sumsq[threadIdx.x] = 0.f;
    }
}

// ---------------------------------------------------------------------------
// kernel 2: persistent half-K-pipelined gather -> HMMA -> warp-private staged
//           row-contiguous scatter
// grid: 294, block 256 (8 warps, 4x2 warp grid of 32x64 output tiles)
// ---------------------------------------------------------------------------
#define PAD_C   136                              // B row: 136 halves = 272 B
#define PAD_H   72                               // A half-row: 72 halves = 144 B
#define SM_MAPS 0                                // 2 slots x 1024 B
#define SM_B    2048                             // 34816 B
#define SM_A0   (SM_B + C * PAD_C * 2)           // 36864, 18432 B (half-K A)
#define SM_A1   (SM_A0 + TILE_M * PAD_H * 2)     // 55296, 18432 B
#define SM_STG  (SM_A1 + TILE_M * PAD_H * 2)     // 73728, 32768 B (8 x 4KB)
#define SM_TOT  (SM_STG + 32768)                 // 106496

__global__ void __launch_bounds__(NTHR, 2)
scatter_gemm(const int* __restrict__ in_maps,
             const int* __restrict__ out_maps,
             float*     __restrict__ out) {
    extern __shared__ char smem[];
    const uint32_t smb = smem_u32(smem);
    const int tid  = threadIdx.x;
    const int wid  = tid >> 5;
    const int lane = tid & 31;

    const int start = blockIdx.x * TPB;
    const int end   = min(start + TPB, TASKS);
    if (start >= end) return;

    // warp/lane constants: 4x2 warp grid of 32x64 tiles
    const int wm = (wid & 3) * 32;
    const int wn = (wid >> 2) * 64;
    const uint32_t aOff = ((uint32_t)(wm + (lane & 15)) * PAD_H + ((lane >> 4) << 3)) * 2;
    const uint32_t bOff = ((uint32_t)(wn + ((lane >> 4) << 3) + (lane & 7)) * PAD_C
                          + (((lane >> 3) & 1) << 3)) * 2;
    const uint32_t bAddr = smb + SM_B + bOff;
    const uint32_t stage = smb + SM_STG + (uint32_t)wid * 4096;   // warp-private

    // cp.async maps(j) into slot j&1 (zero-fill beyond MP tail)
    auto issue_maps = [&](int j) {
        if (tid < 64) {
            const int kq = j / NTILES, tq = j - kq * NTILES;
            const bool isOm = tid >= 32;
            const int c16 = tid & 31;
            const int* src = (isOm ? out_maps : in_maps)
                           + (size_t)kq * MP + (size_t)tq * TILE_M + c16 * 4;
            int nb = min(TILE_M, MP - tq * TILE_M) * 4 - c16 * 16;
            nb = nb < 0 ? 0 : (nb > 16 ? 16 : nb);
            cp16z(smb + SM_MAPS + (uint32_t)(j & 1) * 1024 + (isOm ? 512u : 0u)
                      + (uint32_t)c16 * 16, src, nb);
        }
    };
    // cp.async gather of half-K A(j): 128 rows x 64 cols fp16 -> abase
    auto issue_gather = [&](int j, int half, uint32_t abase) {
        const int* imn = (const int*)(smem + SM_MAPS + (j & 1) * 1024);
#pragma unroll
        for (int it = 0; it < 1024 / NTHR; ++it) {    // 4 iters
            int idx = it * NTHR + tid;
            int row = idx >> 3, c8 = idx & 7;
            cp16(abase + (uint32_t)(row * PAD_H * 2 + c8 * 16),
                 g_fh + (size_t)imn[row] * C + half * 64 + c8 * 8);
        }
    };

    // ---- prologue ----
    issue_maps(start);
    CP_COMMIT();
    CP_WAIT(0);
    __syncthreads();
    issue_gather(start, 0, smb + SM_A0);
    CP_COMMIT();

    int cur_k = -1;
    float acc[2][8][4];

    for (int i = start; i < end; ++i) {
        const int k = i / NTILES;
        const int t = i - k * NTILES;

        CP_WAIT(0);            // h0(i) landed
        __syncthreads();       // visibility; all warps done with A0/A1 reuse

        // prefetch: maps(i+1) + h1(i)   (one commit group)
        if (i + 1 < end) issue_maps(i + 1);
        issue_gather(i, 1, smb + SM_A1);
        CP_COMMIT();

        if (k != cur_k) {      // <=2x per CTA
            const uint4* bg = (const uint4*)(g_wt + (size_t)k * C * C);
#pragma unroll
            for (int it = 0; it < 2048 / NTHR; ++it) {
                int idx = it * NTHR + tid;
                int row = idx >> 4, c8 = idx & 15;
                *(uint4*)(smem + SM_B + (row * PAD_C + c8 * 8) * 2) = bg[idx];
            }
            cur_k = k;
            __syncthreads();
        }

        // ---- init accumulators ----
#pragma unroll
        for (int mb = 0; mb < 2; ++mb)
#pragma unroll
            for (int nbt = 0; nbt < 8; ++nbt)
#pragma unroll
                for (int j = 0; j < 4; ++j) acc[mb][nbt][j] = 0.f;

        // ---- MMA ks 0..3 on A0 ----
        const uint32_t a0Addr = smb + SM_A0 + aOff;
#pragma unroll
        for (int ks = 0; ks < 4; ++ks) {
            const uint32_t kb = ks * 32;
            uint32_t a[2][4];
#pragma unroll
            for (int mb = 0; mb < 2; ++mb)
                ldsm_x4(a[mb][0], a[mb][1], a[mb][2], a[mb][3],
                        a0Addr + mb * (16 * PAD_H * 2) + kb);
            uint32_t b[4][4];
#pragma unroll
            for (int g = 0; g < 4; ++g)
                ldsm_x4(b[g][0], b[g][1], b[g][2], b[g][3],
                        bAddr + g * (16 * PAD_C * 2) + kb);
#pragma unroll
            for (int mb = 0; mb < 2; ++mb)
#pragma unroll
                for (int g = 0; g < 4; ++g) {
                    mma16816(acc[mb][2 * g],     a[mb][0], a[mb][1], a[mb][2], a[mb][3],
                             b[g][0], b[g][1]);
                    mma16816(acc[mb][2 * g + 1], a[mb][0], a[mb][1], a[mb][2], a[mb][3],
                             b[g][2], b[g][3]);
                }
        }

        CP_WAIT(0);            // h1(i) + maps(i+1) landed
        __syncthreads();       // visibility; all warps done ldsm on A0

        // prefetch h0(i+1) into A0
        if (i + 1 < end) {
            issue_gather(i + 1, 0, smb + SM_A0);
            CP_COMMIT();
        }

        // ---- MMA ks 4..7 on A1 ----
        const uint32_t a1Addr = smb + SM_A1 + aOff;
#pragma unroll
        for (int ks = 0; ks < 4; ++ks) {
            const uint32_t kb = ks * 32;
            uint32_t a[2][4];
#pragma unroll
            for (int mb = 0; mb < 2; ++mb)
                ldsm_x4(a[mb][0], a[mb][1], a[mb][2], a[mb][3],
                        a1Addr + mb * (16 * PAD_H * 2) + kb);
            uint32_t b[4][4];
#pragma unroll
            for (int g = 0; g < 4; ++g)
                ldsm_x4(b[g][0], b[g][1], b[g][2], b[g][3],
                        bAddr + g * (16 * PAD_C * 2) + (4 + ks) * 32);
#pragma unroll
            for (int mb = 0; mb < 2; ++mb)
#pragma unroll
                for (int g = 0; g < 4; ++g) {
                    mma16816(acc[mb][2 * g],     a[mb][0], a[mb][1], a[mb][2], a[mb][3],
                             b[g][0], b[g][1]);
                    mma16816(acc[mb][2 * g + 1], a[mb][0], a[mb][1], a[mb][2], a[mb][3],
                             b[g][2], b[g][3]);
                }
        }

        // ---- epilogue: warp-private staging, NO block barrier ----
        const int* om = (const int*)(smem + SM_MAPS + (i & 1) * 1024) + 128;
        const int mvalid = min(TILE_M, MP - t * TILE_M);

        const int rrA = lane >> 2;             // 0..7
        const int p   = lane & 3;
        const int jh  = p & 1;
        const int qr  = lane & 15;             // read: quad index
        const int rhf = lane >> 4;             // read: row half

#pragma unroll
        for (int mb = 0; mb < 2; ++mb) {
#pragma unroll
            for (int nbt = 0; nbt < 8; ++nbt) {
                const int qi = nbt * 2 + (p >> 1);
                const uint32_t sw = (uint32_t)((qi ^ rrA) & 15);
                sts_v2(stage + (uint32_t)rrA * 256 + sw * 16 + (uint32_t)jh * 8,
                       acc[mb][nbt][0], acc[mb][nbt][1]);
                sts_v2(stage + (uint32_t)(rrA + 8) * 256 + sw * 16 + (uint32_t)jh * 8,
                       acc[mb][nbt][2], acc[mb][nbt][3]);
            }
            __syncwarp();
#pragma unroll
            for (int t8 = 0; t8 < 8; ++t8) {
                const int rr = t8 * 2 + rhf;
                float4 v = lds_v4(stage + (uint32_t)rr * 256
                                        + (uint32_t)((qr ^ (rr & 7)) & 15) * 16);
                const int grow = wm + mb * 16 + rr;
                if (grow < mvalid) {
                    float* dst = out + (size_t)om[grow] * C + wn + qr * 4;
                    red_v4(dst, v.x, v.y, v.z, v.w);
                }
            }
            __syncwarp();
        }
    }
}

// ---------------------------------------------------------------------------
// kernel 3: per-channel sum / sumsq (R6 version)
// ---------------------------------------------------------------------------
__global__ void stats_kernel(const float* __restrict__ out) {
    __shared__ float4 ssum[256];
    __shared__ float4 ssq[256];
    const int tid = threadIdx.x;
    const int c4  = tid & 31;
    const int g   = (blockIdx.x * 256 + tid) >> 5;
    const int ng  = (gridDim.x * 256) >> 5;

    float4 s = make_float4(0.f, 0.f, 0.f, 0.f);
    float4 q = make_float4(0.f, 0.f, 0.f, 0.f);
    const float4* o4 = (const float4*)out;
    for (int r = g; r < N_OUT; r += ng) {
        float4 v = o4[(size_t)r * 32 + c4];
        s.x += v.x; s.y += v.y; s.z += v.z; s.w += v.w;
        q.x += v.x * v.x; q.y += v.y * v.y; q.z += v.z * v.z; q.w += v.w * v.w;
    }
    ssum[tid] = s;
    ssq[tid]  = q;
    __syncthreads();
#pragma unroll
    for (int st = 128; st >= 32; st >>= 1) {
        if (tid < st) {
            ssum[tid].x += ssum[tid + st].x; ssum[tid].y += ssum[tid + st].y;
            ssum[tid].z += ssum[tid + st].z; ssum[tid].w += ssum[tid + st].w;
            ssq[tid].x  += ssq[tid + st].x;  ssq[tid].y  += ssq[tid + st].y;
            ssq[tid].z  += ssq[tid + st].z;  ssq[tid].w  += ssq[tid + st].w;
        }
        __syncthreads();
    }
    if (tid < 32) {
        atomicAdd(&g_sum[c4 * 4 + 0], ssum[tid].x);
        atomicAdd(&g_sum[c4 * 4 + 1], ssum[tid].y);
        atomicAdd(&g_sum[c4 * 4 + 2], ssum[tid].z);
        atomicAdd(&g_sum[c4 * 4 + 3], ssum[tid].w);
        atomicAdd(&g_sumsq[c4 * 4 + 0], ssq[tid].x);
        atomicAdd(&g_sumsq[c4 * 4 + 1], ssq[tid].y);
        atomicAdd(&g_sumsq[c4 * 4 + 2], ssq[tid].z);
        atomicAdd(&g_sumsq[c4 * 4 + 3], ssq[tid].w);
    }
}

// ---------------------------------------------------------------------------
// kernel 4: normalize (finalize folded in per-block) — R6 version
// ---------------------------------------------------------------------------
__global__ void norm_kernel(float* __restrict__ out,
                            const float* __restrict__ gamma,
                            const float* __restrict__ beta) {
    __shared__ float sc[C], sh[C];
    if (threadIdx.x < C) {
        const int c = threadIdx.x;
        const float inv_n = 1.0f / (float)N_OUT;
        float mean = g_sum[c] * inv_n;
        float var  = g_sumsq[c] * inv_n - mean * mean;
        float s    = rsqrtf(var + EPS) * gamma[c];
        sc[c] = s;
        sh[c] = beta[c] - mean * s;
    }
    __syncthreads();

    const size_t n4 = (size_t)N_OUT * (C / 4);
    const size_t stride = (size_t)gridDim.x * blockDim.x;
    for (size_t i = (size_t)blockIdx.x * blockDim.x + threadIdx.x; i < n4; i += stride) {
        int c4 = (int)(i & 31);
        float4 v = ((float4*)out)[i];
        float4 s = *(float4*)(sc + c4 * 4);
        float4 h = *(float4*)(sh + c4 * 4);
        v.x = v.x * s.x + h.x;
        v.y = v.y * s.y + h.y;
        v.z = v.z * s.z + h.z;
        v.w = v.w * s.w + h.w;
        ((float4*)out)[i] = v;
    }
}

// ---------------------------------------------------------------------------
// launch
// ---------------------------------------------------------------------------
extern "C" void kernel_launch(void* const* d_in, const int* in_sizes, int n_in,
                              void* d_out, int out_size) {
    const float* feats    = (const float*)d_in[0];
    const float* W        = (const float*)d_in[1];
    const float* gamma    = (const float*)d_in[2];
    const float* beta     = (const float*)d_in[3];
    const int*   in_maps  = (const int*)d_in[4];
    const int*   out_maps = (const int*)d_in[5];
    float* out = (float*)d_out;

    cudaFuncSetAttribute(scatter_gemm,
                         cudaFuncAttributeMaxDynamicSharedMemorySize, SM_TOT);

    prep_kernel<<<1184, 256>>>(out, feats, W);
    scatter_gemm<<<GRID_MAIN, NTHR, SM_TOT>>>(in_maps, out_maps, out);
    stats_kernel<<<1184, 256>>>(out);
    norm_kernel<<<1184, 256>>>(out, gamma, beta);
}

// round 11
// speedup vs baseline: 1.0297x; 1.0297x over previous
#include <cuda_runtime.h>
#include <cuda_fp16.h>
#include <cstdint>

#define N_IN   200000
#define N_OUT  400000
#define K3     27
#define MP     100000
#define C      128
#define EPS    1e-5f

#define TILE_M 128
#define NTHR   256
#define NTILES 782                           // ceil(MP/128)
#define TASKS  (K3 * NTILES)                 // 21114
#define TPB    72
#define GRID_MAIN ((TASKS + TPB - 1) / TPB)  // 294

// ---------------------------------------------------------------------------
// persistent device scratch (allocations are forbidden)
// ---------------------------------------------------------------------------
__device__ float g_sum[C];
__device__ float g_sumsq[C];

__device__ __half g_fh[(size_t)N_IN * C];      // feats, fp16
__device__ __half g_wt[(size_t)K3 * C * C];    // W^T: [k][n(c_out)][c_in], fp16

// ---------------------------------------------------------------------------
// helpers
// ---------------------------------------------------------------------------
__device__ __forceinline__ uint32_t smem_u32(const void* p) {
    uint32_t a;
    asm("{ .reg .u64 t; cvta.to.shared.u64 t, %1; cvt.u32.u64 %0, t; }"
        : "=r"(a) : "l"(p));
    return a;
}
__device__ __forceinline__ void red_v4(float* p, float a, float b, float c, float d) {
    asm volatile("red.global.add.v4.f32 [%0], {%1, %2, %3, %4};"
                 :: "l"(p), "f"(a), "f"(b), "f"(c), "f"(d) : "memory");
}
__device__ __forceinline__ void ldsm_x4(uint32_t& r0, uint32_t& r1,
                                        uint32_t& r2, uint32_t& r3, uint32_t addr) {
    asm volatile("ldmatrix.sync.aligned.m8n8.x4.shared.b16 {%0,%1,%2,%3}, [%4];"
                 : "=r"(r0), "=r"(r1), "=r"(r2), "=r"(r3) : "r"(addr));
}
__device__ __forceinline__ void mma16816(float* c, uint32_t a0, uint32_t a1,
                                         uint32_t a2, uint32_t a3,
                                         uint32_t b0, uint32_t b1) {
    asm volatile(
        "mma.sync.aligned.m16n8k16.row.col.f32.f16.f16.f32 "
        "{%0,%1,%2,%3}, {%4,%5,%6,%7}, {%8,%9}, {%0,%1,%2,%3};"
        : "+f"(c[0]), "+f"(c[1]), "+f"(c[2]), "+f"(c[3])
        : "r"(a0), "r"(a1), "r"(a2), "r"(a3), "r"(b0), "r"(b1));
}
// gather copy with L2 evict_last residency hint (keeps g_fh resident in L2
// against the scatter's eviction pressure)
__device__ __forceinline__ void cp16_resident(uint32_t dst, const void* src,
                                              uint64_t pol) {
    asm volatile("cp.async.cg.shared.global.L2::cache_hint [%0], [%1], 16, %2;"
                 :: "r"(dst), "l"(src), "l"(pol) : "memory");
}
__device__ __forceinline__ void cp16z(uint32_t dst, const void* src, int nbytes) {
    asm volatile("cp.async.ca.shared.global [%0], [%1], 16, %2;"
                 :: "r"(dst), "l"(src), "r"(nbytes) : "memory");
}
#define CP_COMMIT()  asm volatile("cp.async.commit_group;" ::: "memory")
#define CP_WAIT(N)   asm volatile("cp.async.wait_group %0;" :: "n"(N) : "memory")

__device__ __forceinline__ void sts_v2(uint32_t addr, float a, float b) {
    asm volatile("st.shared.v2.f32 [%0], {%1, %2};" :: "r"(addr), "f"(a), "f"(b));
}
__device__ __forceinline__ float4 lds_v4(uint32_t addr) {
    float4 v;
    asm volatile("ld.shared.v4.f32 {%0,%1,%2,%3}, [%4];"
                 : "=f"(v.x), "=f"(v.y), "=f"(v.z), "=f"(v.w) : "r"(addr));
    return v;
}

// ---------------------------------------------------------------------------
// kernel 1: fused prep — zero output+stats, feats->fp16, W transpose->fp16
// ---------------------------------------------------------------------------
__global__ void prep_kernel(float* __restrict__ out,
                            const float* __restrict__ feats,
                            const float* __restrict__ W) {
    const size_t stride = (size_t)gridDim.x * blockDim.x;
    const size_t base = (size_t)blockIdx.x * blockDim.x + threadIdx.x;

    float4 z = make_float4(0.f, 0.f, 0.f, 0.f);
    for (size_t i = base; i < (size_t)N_OUT * (C / 4); i += stride)
        ((float4*)out)[i] = z;

    for (size_t i = base; i < (size_t)N_IN * (C / 4); i += stride) {
        float4 v = ((const float4*)feats)[i];
        __half h[4];
        h[0] = __float2half_rn(v.x);
        h[1] = __float2half_rn(v.y);
        h[2] = __float2half_rn(v.z);
        h[3] = __float2half_rn(v.w);
        ((uint2*)g_fh)[i] = *(uint2*)h;
    }

    for (size_t i = base; i < (size_t)K3 * C * C; i += stride) {
        int c  = (int)(i & (C - 1));
        int nn = (int)((i >> 7) & (C - 1));
        int k  = (int)(i >> 14);
        g_wt[i] = __float2half_rn(W[(size_t)k * C * C + (size_t)c * C + nn]);
    }

    if (blockIdx.x == 0 && threadIdx.x < C) {
        g_sum[threadIdx.x]   = 0.f;
        g_sumsq[threadIdx.x] = 0.f;
    }
}

// ---------------------------------------------------------------------------
// kernel 2: persistent pipelined gather -> HMMA -> staged row-contig scatter
// grid: 294, block 256 (8 warps, 4x2 warp grid of 32x64 output tiles)
// ---------------------------------------------------------------------------
#define PAD_C   136
#define SM_MAPS 0                                 // 3 slots x 1024 B
#define SM_B    3072                              // 34816 B
#define SM_A0   (SM_B + C * PAD_C * 2)            // 37888
#define SM_A1   (SM_A0 + TILE_M * PAD_C * 2)      // 72704
#define SM_TOT  (SM_A1 + TILE_M * PAD_C * 2)      // 107520

__global__ void __launch_bounds__(NTHR, 2)
scatter_gemm(const int* __restrict__ in_maps,
             const int* __restrict__ out_maps,
             float*     __restrict__ out) {
    extern __shared__ char smem[];
    const uint32_t smb = smem_u32(smem);
    const int tid  = threadIdx.x;
    const int wid  = tid >> 5;
    const int lane = tid & 31;

    const int start = blockIdx.x * TPB;
    const int end   = min(start + TPB, TASKS);
    if (start >= end) return;

    // L2 evict_last policy for the feature gather
    uint64_t pol;
    asm("createpolicy.fractional.L2::evict_last.b64 %0, 1.0;" : "=l"(pol));

    // warp/lane constants: 4x2 warp grid of 32x64 tiles
    const int wm = (wid & 3) * 32;
    const int wn = (wid >> 2) * 64;
    const uint32_t aOff = ((uint32_t)(wm + (lane & 15)) * PAD_C + ((lane >> 4) << 3)) * 2;
    const uint32_t bOff = ((uint32_t)(wn + ((lane >> 4) << 3) + (lane & 7)) * PAD_C
                          + (((lane >> 3) & 1) << 3)) * 2;

    // cp.async maps(j) into slot j%3 (zero-fill beyond MP tail)
    auto issue_maps = [&](int j) {
        if (tid < 64) {
            const int kq = j / NTILES, tq = j - kq * NTILES;
            const bool isOm = tid >= 32;
            const int c16 = tid & 31;
            const int* src = (isOm ? out_maps : in_maps)
                           + (size_t)kq * MP + (size_t)tq * TILE_M + c16 * 4;
            int nb = min(TILE_M, MP - tq * TILE_M) * 4 - c16 * 16;
            nb = nb < 0 ? 0 : (nb > 16 ? 16 : nb);
            cp16z(smb + SM_MAPS + (uint32_t)(j % 3) * 1024 + (isOm ? 512u : 0u)
                      + (uint32_t)c16 * 16, src, nb);
        }
    };
    auto issue_gather = [&](int j, uint32_t abase) {
        const int* imn = (const int*)(smem + SM_MAPS + (j % 3) * 1024);
#pragma unroll
        for (int it = 0; it < 2048 / NTHR; ++it) {    // 8 iters
            int idx = it * NTHR + tid;
            int row = idx >> 4, c8 = idx & 15;
            cp16_resident(abase + (uint32_t)(row * PAD_C + c8 * 8) * 2,
                          g_fh + (size_t)imn[row] * C + c8 * 8, pol);
        }
    };

    // ---- prologue ----
    issue_maps(start);
    CP_COMMIT();
    CP_WAIT(0);
    __syncthreads();
    issue_gather(start, smb + SM_A0);
    if (start + 1 < end) issue_maps(start + 1);
    CP_COMMIT();

    int cur_k = -1;

    for (int i = start; i < end; ++i) {
        const int k = i / NTILES;
        const int t = i - k * NTILES;
        const int buf = i & 1;

        CP_WAIT(0);            // A(i) + maps(i+1) landed
        __syncthreads();       // cross-warp visibility; protects reused buffers

        if (k != cur_k) {      // <=2x per CTA
            const uint4* bg = (const uint4*)(g_wt + (size_t)k * C * C);
#pragma unroll
            for (int it = 0; it < 2048 / NTHR; ++it) {
                int idx = it * NTHR + tid;
                int row = idx >> 4, c8 = idx & 15;
                *(uint4*)(smem + SM_B + (row * PAD_C + c8 * 8) * 2) = bg[idx];
            }
            cur_k = k;
            __syncthreads();
        }

        // prefetch next tile: A(i+1) + maps(i+2)
        if (i + 1 < end) {
            issue_gather(i + 1, smb + (buf ? SM_A0 : SM_A1));
            if (i + 2 < end) issue_maps(i + 2);
            CP_COMMIT();
        }

        // ---- MMA mainloop on A[buf] ----
        const uint32_t aAddr = smb + (buf ? SM_A1 : SM_A0) + aOff;
        const uint32_t bAddr = smb + SM_B + bOff;

        float acc[2][8][4];
#pragma unroll
        for (int mb = 0; mb < 2; ++mb)
#pragma unroll
            for (int nbt = 0; nbt < 8; ++nbt)
#pragma unroll
                for (int j = 0; j < 4; ++j) acc[mb][nbt][j] = 0.f;

#pragma unroll
        for (int ks = 0; ks < 8; ++ks) {
            const uint32_t kb = ks * 32;
            uint32_t a[2][4];
#pragma unroll
            for (int mb = 0; mb < 2; ++mb)
                ldsm_x4(a[mb][0], a[mb][1], a[mb][2], a[mb][3],
                        aAddr + mb * (16 * PAD_C * 2) + kb);
            uint32_t b[4][4];
#pragma unroll
            for (int g = 0; g < 4; ++g)
                ldsm_x4(b[g][0], b[g][1], b[g][2], b[g][3],
                        bAddr + g * (16 * PAD_C * 2) + kb);
#pragma unroll
            for (int mb = 0; mb < 2; ++mb)
#pragma unroll
                for (int g = 0; g < 4; ++g) {
                    mma16816(acc[mb][2 * g],     a[mb][0], a[mb][1], a[mb][2], a[mb][3],
                             b[g][0], b[g][1]);
                    mma16816(acc[mb][2 * g + 1], a[mb][0], a[mb][1], a[mb][2], a[mb][3],
                             b[g][2], b[g][3]);
                }
        }

        __syncthreads();       // A[buf] dead for ALL warps -> usable as staging

        // ---- epilogue: stage per-warp 16x64 fp32 halves, scatter row-contig ----
        const int* om = (const int*)(smem + SM_MAPS + (i % 3) * 1024) + 128;
        const int mvalid = min(TILE_M, MP - t * TILE_M);
        const uint32_t stage = smb + (buf ? SM_A1 : SM_A0) + (uint32_t)wid * 4096;

        const int rrA = lane >> 2;             // 0..7
        const int p   = lane & 3;
        const int jh  = p & 1;
        const int qr  = lane & 15;             // read: quad index
        const int rhf = lane >> 4;             // read: row half

#pragma unroll
        for (int mb = 0; mb < 2; ++mb) {
#pragma unroll
            for (int nbt = 0; nbt < 8; ++nbt) {
                const int qi = nbt * 2 + (p >> 1);
                const uint32_t sw = (uint32_t)((qi ^ rrA) & 15);
                sts_v2(stage + (uint32_t)rrA * 256 + sw * 16 + (uint32_t)jh * 8,
                       acc[mb][nbt][0], acc[mb][nbt][1]);
                sts_v2(stage + (uint32_t)(rrA + 8) * 256 + sw * 16 + (uint32_t)jh * 8,
                       acc[mb][nbt][2], acc[mb][nbt][3]);
            }
            __syncwarp();
#pragma unroll
            for (int t8 = 0; t8 < 8; ++t8) {
                const int rr = t8 * 2 + rhf;
                float4 v = lds_v4(stage + (uint32_t)rr * 256
                                        + (uint32_t)((qr ^ (rr & 7)) & 15) * 16);
                const int grow = wm + mb * 16 + rr;
                if (grow < mvalid) {
                    float* dst = out + (size_t)om[grow] * C + wn + qr * 4;
                    red_v4(dst, v.x, v.y, v.z, v.w);
                }
            }
            __syncwarp();
        }
    }
}

// ---------------------------------------------------------------------------
// kernel 3: per-channel sum / sumsq
// ---------------------------------------------------------------------------
__global__ void stats_kernel(const float* __restrict__ out) {
    __shared__ float4 ssum[256];
    __shared__ float4 ssq[256];
    const int tid = threadIdx.x;
    const int c4  = tid & 31;
    const int g   = (blockIdx.x * 256 + tid) >> 5;
    const int ng  = (gridDim.x * 256) >> 5;

    float4 s = make_float4(0.f, 0.f, 0.f, 0.f);
    float4 q = make_float4(0.f, 0.f, 0.f, 0.f);
    const float4* o4 = (const float4*)out;
    for (int r = g; r < N_OUT; r += ng) {
        float4 v = o4[(size_t)r * 32 + c4];
        s.x += v.x; s.y += v.y; s.z += v.z; s.w += v.w;
        q.x += v.x * v.x; q.y += v.y * v.y; q.z += v.z * v.z; q.w += v.w * v.w;
    }
    ssum[tid] = s;
    ssq[tid]  = q;
    __syncthreads();
#pragma unroll
    for (int st = 128; st >= 32; st >>= 1) {
        if (tid < st) {
            ssum[tid].x += ssum[tid + st].x; ssum[tid].y += ssum[tid + st].y;
            ssum[tid].z += ssum[tid + st].z; ssum[tid].w += ssum[tid + st].w;
            ssq[tid].x  += ssq[tid + st].x;  ssq[tid].y  += ssq[tid + st].y;
            ssq[tid].z  += ssq[tid + st].z;  ssq[tid].w  += ssq[tid + st].w;
        }
        __syncthreads();
    }
    if (tid < 32) {
        atomicAdd(&g_sum[c4 * 4 + 0], ssum[tid].x);
        atomicAdd(&g_sum[c4 * 4 + 1], ssum[tid].y);
        atomicAdd(&g_sum[c4 * 4 + 2], ssum[tid].z);
        atomicAdd(&g_sum[c4 * 4 + 3], ssum[tid].w);
        atomicAdd(&g_sumsq[c4 * 4 + 0], ssq[tid].x);
        atomicAdd(&g_sumsq[c4 * 4 + 1], ssq[tid].y);
        atomicAdd(&g_sumsq[c4 * 4 + 2], ssq[tid].z);
        atomicAdd(&g_sumsq[c4 * 4 + 3], ssq[tid].w);
    }
}

// ---------------------------------------------------------------------------
// kernel 4: normalize (finalize folded in per-block)
// ---------------------------------------------------------------------------
__global__ void norm_kernel(float* __restrict__ out,
                            const float* __restrict__ gamma,
                            const float* __restrict__ beta) {
    __shared__ float sc[C], sh[C];
    if (threadIdx.x < C) {
        const int c = threadIdx.x;
        const float inv_n = 1.0f / (float)N_OUT;
        float mean = g_sum[c] * inv_n;
        float var  = g_sumsq[c] * inv_n - mean * mean;
        float s    = rsqrtf(var + EPS) * gamma[c];
        sc[c] = s;
        sh[c] = beta[c] - mean * s;
    }
    __syncthreads();

    const size_t n4 = (size_t)N_OUT * (C / 4);
    const size_t stride = (size_t)gridDim.x * blockDim.x;
    for (size_t i = (size_t)blockIdx.x * blockDim.x + threadIdx.x; i < n4; i += stride) {
        int c4 = (int)(i & 31);
        float4 v = ((float4*)out)[i];
        float4 s = *(float4*)(sc + c4 * 4);
        float4 h = *(float4*)(sh + c4 * 4);
        v.x = v.x * s.x + h.x;
        v.y = v.y * s.y + h.y;
        v.z = v.z * s.z + h.z;
        v.w = v.w * s.w + h.w;
        ((float4*)out)[i] = v;
    }
}

// ---------------------------------------------------------------------------
// launch
// ---------------------------------------------------------------------------
extern "C" void kernel_launch(void* const* d_in, const int* in_sizes, int n_in,
                              void* d_out, int out_size) {
    const float* feats    = (const float*)d_in[0];
    const float* W        = (const float*)d_in[1];
    const float* gamma    = (const float*)d_in[2];
    const float* beta     = (const float*)d_in[3];
    const int*   in_maps  = (const int*)d_in[4];
    const int*   out_maps = (const int*)d_in[5];
    float* out = (float*)d_out;

    cudaFuncSetAttribute(scatter_gemm,
                         cudaFuncAttributeMaxDynamicSharedMemorySize, SM_TOT);

    prep_kernel<<<1184, 256>>>(out, feats, W);
    scatter_gemm<<<GRID_MAIN, NTHR, SM_TOT>>>(in_maps, out_maps, out);
    stats_kernel<<<1184, 256>>>(out);
    norm_kernel<<<1184, 256>>>(out, gamma, beta);
}

// round 12
// speedup vs baseline: 1.0685x; 1.0377x over previous
#include <cuda_runtime.h>
#include <cuda_fp16.h>
#include <cstdint>

#define N_IN   200000
#define N_OUT  400000
#define K3     27
#define MP     100000
#define C      128
#define EPS    1e-5f

#define TILE_M 128
#define NTHR   256
#define NTILES 782                           // ceil(MP/128)
#define TASKS  (K3 * NTILES)                 // 21114
#define TPB    72
#define GRID_MAIN ((TASKS + TPB - 1) / TPB)  // 294

// ---------------------------------------------------------------------------
// persistent device scratch (allocations are forbidden)
// ---------------------------------------------------------------------------
__device__ float g_sum[C];
__device__ float g_sumsq[C];

__device__ __half g_fh[(size_t)N_IN * C];      // feats, fp16
__device__ __half g_wt[(size_t)K3 * C * C];    // W^T: [k][n(c_out)][c_in], fp16

// ---------------------------------------------------------------------------
// helpers
// ---------------------------------------------------------------------------
__device__ __forceinline__ uint32_t smem_u32(const void* p) {
    uint32_t a;
    asm("{ .reg .u64 t; cvta.to.shared.u64 t, %1; cvt.u32.u64 %0, t; }"
        : "=r"(a) : "l"(p));
    return a;
}
__device__ __forceinline__ void red_v4(float* p, float a, float b, float c, float d) {
    asm volatile("red.global.add.v4.f32 [%0], {%1, %2, %3, %4};"
                 :: "l"(p), "f"(a), "f"(b), "f"(c), "f"(d) : "memory");
}
__device__ __forceinline__ void ldsm_x4(uint32_t& r0, uint32_t& r1,
                                        uint32_t& r2, uint32_t& r3, uint32_t addr) {
    asm volatile("ldmatrix.sync.aligned.m8n8.x4.shared.b16 {%0,%1,%2,%3}, [%4];"
                 : "=r"(r0), "=r"(r1), "=r"(r2), "=r"(r3) : "r"(addr));
}
__device__ __forceinline__ void mma16816(float* c, uint32_t a0, uint32_t a1,
                                         uint32_t a2, uint32_t a3,
                                         uint32_t b0, uint32_t b1) {
    asm volatile(
        "mma.sync.aligned.m16n8k16.row.col.f32.f16.f16.f32 "
        "{%0,%1,%2,%3}, {%4,%5,%6,%7}, {%8,%9}, {%0,%1,%2,%3};"
        : "+f"(c[0]), "+f"(c[1]), "+f"(c[2]), "+f"(c[3])
        : "r"(a0), "r"(a1), "r"(a2), "r"(a3), "r"(b0), "r"(b1));
}
__device__ __forceinline__ void cp16(uint32_t dst, const void* src) {
    asm volatile("cp.async.cg.shared.global [%0], [%1], 16;"
                 :: "r"(dst), "l"(src) : "memory");
}
__device__ __forceinline__ void cp16z(uint32_t dst, const void* src, int nbytes) {
    asm volatile("cp.async.ca.shared.global [%0], [%1], 16, %2;"
                 :: "r"(dst), "l"(src), "r"(nbytes) : "memory");
}
#define CP_COMMIT()  asm volatile("cp.async.commit_group;" ::: "memory")
#define CP_WAIT(N)   asm volatile("cp.async.wait_group %0;" :: "n"(N) : "memory")

__device__ __forceinline__ void sts_v2(uint32_t addr, float a, float b) {
    asm volatile("st.shared.v2.f32 [%0], {%1, %2};" :: "r"(addr), "f"(a), "f"(b));
}
__device__ __forceinline__ float4 lds_v4(uint32_t addr) {
    float4 v;
    asm volatile("ld.shared.v4.f32 {%0,%1,%2,%3}, [%4];"
                 : "=f"(v.x), "=f"(v.y), "=f"(v.z), "=f"(v.w) : "r"(addr));
    return v;
}

// ---------------------------------------------------------------------------
// kernel 1: fused prep — zero output+stats, feats->fp16, W transpose->fp16
// ---------------------------------------------------------------------------
__global__ void prep_kernel(float* __restrict__ out,
                            const float* __restrict__ feats,
                            const float* __restrict__ W) {
    const size_t stride = (size_t)gridDim.x * blockDim.x;
    const size_t base = (size_t)blockIdx.x * blockDim.x + threadIdx.x;

    float4 z = make_float4(0.f, 0.f, 0.f, 0.f);
    for (size_t i = base; i < (size_t)N_OUT * (C / 4); i += stride)
        ((float4*)out)[i] = z;

    for (size_t i = base; i < (size_t)N_IN * (C / 4); i += stride) {
        float4 v = ((const float4*)feats)[i];
        __half h[4];
        h[0] = __float2half_rn(v.x);
        h[1] = __float2half_rn(v.y);
        h[2] = __float2half_rn(v.z);
        h[3] = __float2half_rn(v.w);
        ((uint2*)g_fh)[i] = *(uint2*)h;
    }

    for (size_t i = base; i < (size_t)K3 * C * C; i += stride) {
        int c  = (int)(i & (C - 1));
        int nn = (int)((i >> 7) & (C - 1));
        int k  = (int)(i >> 14);
        g_wt[i] = __float2half_rn(W[(size_t)k * C * C + (size_t)c * C + nn]);
    }

    if (blockIdx.x == 0 && threadIdx.x < C) {
        g_sum[threadIdx.x]   = 0.f;
        g_sumsq[threadIdx.x] = 0.f;
    }
}

// ---------------------------------------------------------------------------
// kernel 2: persistent pipelined gather -> HMMA -> staged row-contig scatter
// grid: 294, block 256 (8 warps, 4x2 warp grid of 32x64 output tiles)
// ---------------------------------------------------------------------------
#define PAD_C   136
#define SM_MAPS 0                                 // 3 slots x 1024 B
#define SM_B    3072                              // 34816 B
#define SM_A0   (SM_B + C * PAD_C * 2)            // 37888
#define SM_A1   (SM_A0 + TILE_M * PAD_C * 2)      // 72704
#define SM_TOT  (SM_A1 + TILE_M * PAD_C * 2)      // 107520

__global__ void __launch_bounds__(NTHR, 2)
scatter_gemm(const int* __restrict__ in_maps,
             const int* __restrict__ out_maps,
             float*     __restrict__ out) {
    extern __shared__ char smem[];
    const uint32_t smb = smem_u32(smem);
    const int tid  = threadIdx.x;
    const int wid  = tid >> 5;
    const int lane = tid & 31;

    const int start = blockIdx.x * TPB;
    const int end   = min(start + TPB, TASKS);
    if (start >= end) return;

    // warp/lane constants: 4x2 warp grid of 32x64 tiles
    const int wm = (wid & 3) * 32;
    const int wn = (wid >> 2) * 64;
    const uint32_t aOff = ((uint32_t)(wm + (lane & 15)) * PAD_C + ((lane >> 4) << 3)) * 2;
    const uint32_t bOff = ((uint32_t)(wn + ((lane >> 4) << 3) + (lane & 7)) * PAD_C
                          + (((lane >> 3) & 1) << 3)) * 2;

    // cp.async maps(j) into slot j%3 (zero-fill beyond MP tail)
    auto issue_maps = [&](int j) {
        if (tid < 64) {
            const int kq = j / NTILES, tq = j - kq * NTILES;
            const bool isOm = tid >= 32;
            const int c16 = tid & 31;
            const int* src = (isOm ? out_maps : in_maps)
                           + (size_t)kq * MP + (size_t)tq * TILE_M + c16 * 4;
            int nb = min(TILE_M, MP - tq * TILE_M) * 4 - c16 * 16;
            nb = nb < 0 ? 0 : (nb > 16 ? 16 : nb);
            cp16z(smb + SM_MAPS + (uint32_t)(j % 3) * 1024 + (isOm ? 512u : 0u)
                      + (uint32_t)c16 * 16, src, nb);
        }
    };
    auto issue_gather = [&](int j, uint32_t abase) {
        const int* imn = (const int*)(smem + SM_MAPS + (j % 3) * 1024);
#pragma unroll
        for (int it = 0; it < 2048 / NTHR; ++it) {    // 8 iters
            int idx = it * NTHR + tid;
            int row = idx >> 4, c8 = idx & 15;
            cp16(abase + (uint32_t)(row * PAD_C + c8 * 8) * 2,
                 g_fh + (size_t)imn[row] * C + c8 * 8);
        }
    };

    // ---- prologue ----
    issue_maps(start);
    CP_COMMIT();
    CP_WAIT(0);
    __syncthreads();
    issue_gather(start, smb + SM_A0);
    if (start + 1 < end) issue_maps(start + 1);
    CP_COMMIT();

    int cur_k = -1;

    for (int i = start; i < end; ++i) {
        const int k = i / NTILES;
        const int t = i - k * NTILES;
        const int buf = i & 1;

        CP_WAIT(0);            // A(i) + maps(i+1) landed
        __syncthreads();       // cross-warp visibility; protects reused buffers

        if (k != cur_k) {      // <=2x per CTA
            const uint4* bg = (const uint4*)(g_wt + (size_t)k * C * C);
#pragma unroll
            for (int it = 0; it < 2048 / NTHR; ++it) {
                int idx = it * NTHR + tid;
                int row = idx >> 4, c8 = idx & 15;
                *(uint4*)(smem + SM_B + (row * PAD_C + c8 * 8) * 2) = bg[idx];
            }
            cur_k = k;
            __syncthreads();
        }

        // prefetch next tile: A(i+1) + maps(i+2)
        if (i + 1 < end) {
            issue_gather(i + 1, smb + (buf ? SM_A0 : SM_A1));
            if (i + 2 < end) issue_maps(i + 2);
            CP_COMMIT();
        }

        // ---- MMA mainloop on A[buf] ----
        const uint32_t aAddr = smb + (buf ? SM_A1 : SM_A0) + aOff;
        const uint32_t bAddr = smb + SM_B + bOff;

        float acc[2][8][4];
#pragma unroll
        for (int mb = 0; mb < 2; ++mb)
#pragma unroll
            for (int nbt = 0; nbt < 8; ++nbt)
#pragma unroll
                for (int j = 0; j < 4; ++j) acc[mb][nbt][j] = 0.f;

#pragma unroll
        for (int ks = 0; ks < 8; ++ks) {
            const uint32_t kb = ks * 32;
            uint32_t a[2][4];
#pragma unroll
            for (int mb = 0; mb < 2; ++mb)
                ldsm_x4(a[mb][0], a[mb][1], a[mb][2], a[mb][3],
                        aAddr + mb * (16 * PAD_C * 2) + kb);
            uint32_t b[4][4];
#pragma unroll
            for (int g = 0; g < 4; ++g)
                ldsm_x4(b[g][0], b[g][1], b[g][2], b[g][3],
                        bAddr + g * (16 * PAD_C * 2) + kb);
#pragma unroll
            for (int mb = 0; mb < 2; ++mb)
#pragma unroll
                for (int g = 0; g < 4; ++g) {
                    mma16816(acc[mb][2 * g],     a[mb][0], a[mb][1], a[mb][2], a[mb][3],
                             b[g][0], b[g][1]);
                    mma16816(acc[mb][2 * g + 1], a[mb][0], a[mb][1], a[mb][2], a[mb][3],
                             b[g][2], b[g][3]);
                }
        }

        __syncthreads();       // A[buf] dead for ALL warps -> usable as staging

        // ---- epilogue: stage per-warp 16x64 fp32 halves, scatter row-contig ----
        const int* om = (const int*)(smem + SM_MAPS + (i % 3) * 1024) + 128;
        const int mvalid = min(TILE_M, MP - t * TILE_M);
        const uint32_t stage = smb + (buf ? SM_A1 : SM_A0) + (uint32_t)wid * 4096;

        const int rrA = lane >> 2;             // 0..7
        const int p   = lane & 3;
        const int jh  = p & 1;
        const int qr  = lane & 15;             // read: quad index
        const int rhf = lane >> 4;             // read: row half

#pragma unroll
        for (int mb = 0; mb < 2; ++mb) {
#pragma unroll
            for (int nbt = 0; nbt < 8; ++nbt) {
                const int qi = nbt * 2 + (p >> 1);
                const uint32_t sw = (uint32_t)((qi ^ rrA) & 15);
                sts_v2(stage + (uint32_t)rrA * 256 + sw * 16 + (uint32_t)jh * 8,
                       acc[mb][nbt][0], acc[mb][nbt][1]);
                sts_v2(stage + (uint32_t)(rrA + 8) * 256 + sw * 16 + (uint32_t)jh * 8,
                       acc[mb][nbt][2], acc[mb][nbt][3]);
            }
            __syncwarp();
#pragma unroll
            for (int t8 = 0; t8 < 8; ++t8) {
                const int rr = t8 * 2 + rhf;
                float4 v = lds_v4(stage + (uint32_t)rr * 256
                                        + (uint32_t)((qr ^ (rr & 7)) & 15) * 16);
                const int grow = wm + mb * 16 + rr;
                if (grow < mvalid) {
                    float* dst = out + (size_t)om[grow] * C + wn + qr * 4;
                    red_v4(dst, v.x, v.y, v.z, v.w);
                }
            }
            __syncwarp();
        }
    }
}

// ---------------------------------------------------------------------------
// kernel 3: per-channel sum / sumsq (forward stream; leaves tail of `out`
// resident in L2 for the reverse-order norm pass)
// ---------------------------------------------------------------------------
__global__ void stats_kernel(const float* __restrict__ out) {
    __shared__ float4 ssum[256];
    __shared__ float4 ssq[256];
    const int tid = threadIdx.x;
    const int c4  = tid & 31;
    const int g   = (blockIdx.x * 256 + tid) >> 5;
    const int ng  = (gridDim.x * 256) >> 5;

    float4 s = make_float4(0.f, 0.f, 0.f, 0.f);
    float4 q = make_float4(0.f, 0.f, 0.f, 0.f);
    const float4* o4 = (const float4*)out;
    for (int r = g; r < N_OUT; r += ng) {
        float4 v = o4[(size_t)r * 32 + c4];
        s.x += v.x; s.y += v.y; s.z += v.z; s.w += v.w;
        q.x += v.x * v.x; q.y += v.y * v.y; q.z += v.z * v.z; q.w += v.w * v.w;
    }
    ssum[tid] = s;
    ssq[tid]  = q;
    __syncthreads();
#pragma unroll
    for (int st = 128; st >= 32; st >>= 1) {
        if (tid < st) {
            ssum[tid].x += ssum[tid + st].x; ssum[tid].y += ssum[tid + st].y;
            ssum[tid].z += ssum[tid + st].z; ssum[tid].w += ssum[tid + st].w;
            ssq[tid].x  += ssq[tid + st].x;  ssq[tid].y  += ssq[tid + st].y;
            ssq[tid].z  += ssq[tid + st].z;  ssq[tid].w  += ssq[tid + st].w;
        }
        __syncthreads();
    }
    if (tid < 32) {
        atomicAdd(&g_sum[c4 * 4 + 0], ssum[tid].x);
        atomicAdd(&g_sum[c4 * 4 + 1], ssum[tid].y);
        atomicAdd(&g_sum[c4 * 4 + 2], ssum[tid].z);
        atomicAdd(&g_sum[c4 * 4 + 3], ssum[tid].w);
        atomicAdd(&g_sumsq[c4 * 4 + 0], ssq[tid].x);
        atomicAdd(&g_sumsq[c4 * 4 + 1], ssq[tid].y);
        atomicAdd(&g_sumsq[c4 * 4 + 2], ssq[tid].z);
        atomicAdd(&g_sumsq[c4 * 4 + 3], ssq[tid].w);
    }
}

// ---------------------------------------------------------------------------
// kernel 4: normalize — REVERSE traversal so the first reads hit the L2-
// resident tail left behind by stats_kernel's forward stream
// ---------------------------------------------------------------------------
__global__ void norm_kernel(float* __restrict__ out,
                            const float* __restrict__ gamma,
                            const float* __restrict__ beta) {
    __shared__ float sc[C], sh[C];
    if (threadIdx.x < C) {
        const int c = threadIdx.x;
        const float inv_n = 1.0f / (float)N_OUT;
        float mean = g_sum[c] * inv_n;
        float var  = g_sumsq[c] * inv_n - mean * mean;
        float s    = rsqrtf(var + EPS) * gamma[c];
        sc[c] = s;
        sh[c] = beta[c] - mean * s;
    }
    __syncthreads();

    const size_t n4 = (size_t)N_OUT * (C / 4);
    const size_t stride = (size_t)gridDim.x * blockDim.x;
    for (size_t j = (size_t)blockIdx.x * blockDim.x + threadIdx.x; j < n4; j += stride) {
        const size_t i = n4 - 1 - j;           // reverse order, still coalesced
        int c4 = (int)(i & 31);
        float4 v = ((float4*)out)[i];
        float4 s = *(float4*)(sc + c4 * 4);
        float4 h = *(float4*)(sh + c4 * 4);
        v.x = v.x * s.x + h.x;
        v.y = v.y * s.y + h.y;
        v.z = v.z * s.z + h.z;
        v.w = v.w * s.w + h.w;
        ((float4*)out)[i] = v;
    }
}

// ---------------------------------------------------------------------------
// launch
// ---------------------------------------------------------------------------
extern "C" void kernel_launch(void* const* d_in, const int* in_sizes, int n_in,
                              void* d_out, int out_size) {
    const float* feats    = (const float*)d_in[0];
    const float* W        = (const float*)d_in[1];
    const float* gamma    = (const float*)d_in[2];
    const float* beta     = (const float*)d_in[3];
    const int*   in_maps  = (const int*)d_in[4];
    const int*   out_maps = (const int*)d_in[5];
    float* out = (float*)d_out;

    cudaFuncSetAttribute(scatter_gemm,
                         cudaFuncAttributeMaxDynamicSharedMemorySize, SM_TOT);

    prep_kernel<<<1184, 256>>>(out, feats, W);
    scatter_gemm<<<GRID_MAIN, NTHR, SM_TOT>>>(in_maps, out_maps, out);
    stats_kernel<<<1184, 256>>>(out);
    norm_kernel<<<1184, 256>>>(out, gamma, beta);
}

// round 13
// speedup vs baseline: 1.0793x; 1.0101x over previous
#include <cuda_runtime.h>
#include <cuda_fp16.h>
#include <cstdint>

#define N_IN   200000
#define N_OUT  400000
#define K3     27
#define MP     100000
#define C      128
#define EPS    1e-5f

#define TILE_M 128
#define NTHR   256
#define NTILES 782                           // ceil(MP/128)
#define TASKS  (K3 * NTILES)                 // 21114
#define TPB    72
#define GRID_MAIN ((TASKS + TPB - 1) / TPB)  // 294
#define GRID_BN  592                         // 4 CTAs/SM x 148 — all co-resident

// ---------------------------------------------------------------------------
// persistent device scratch (allocations are forbidden)
// ---------------------------------------------------------------------------
__device__ float g_sum[C];
__device__ float g_sumsq[C];
__device__ unsigned int g_bar;               // grid-barrier counter

__device__ __half g_fh[(size_t)N_IN * C];      // feats, fp16
__device__ __half g_wt[(size_t)K3 * C * C];    // W^T: [k][n(c_out)][c_in], fp16

// ---------------------------------------------------------------------------
// helpers
// ---------------------------------------------------------------------------
__device__ __forceinline__ uint32_t smem_u32(const void* p) {
    uint32_t a;
    asm("{ .reg .u64 t; cvta.to.shared.u64 t, %1; cvt.u32.u64 %0, t; }"
        : "=r"(a) : "l"(p));
    return a;
}
__device__ __forceinline__ void red_v4(float* p, float a, float b, float c, float d) {
    asm volatile("red.global.add.v4.f32 [%0], {%1, %2, %3, %4};"
                 :: "l"(p), "f"(a), "f"(b), "f"(c), "f"(d) : "memory");
}
__device__ __forceinline__ void ldsm_x4(uint32_t& r0, uint32_t& r1,
                                        uint32_t& r2, uint32_t& r3, uint32_t addr) {
    asm volatile("ldmatrix.sync.aligned.m8n8.x4.shared.b16 {%0,%1,%2,%3}, [%4];"
                 : "=r"(r0), "=r"(r1), "=r"(r2), "=r"(r3) : "r"(addr));
}
__device__ __forceinline__ void mma16816(float* c, uint32_t a0, uint32_t a1,
                                         uint32_t a2, uint32_t a3,
                                         uint32_t b0, uint32_t b1) {
    asm volatile(
        "mma.sync.aligned.m16n8k16.row.col.f32.f16.f16.f32 "
        "{%0,%1,%2,%3}, {%4,%5,%6,%7}, {%8,%9}, {%0,%1,%2,%3};"
        : "+f"(c[0]), "+f"(c[1]), "+f"(c[2]), "+f"(c[3])
        : "r"(a0), "r"(a1), "r"(a2), "r"(a3), "r"(b0), "r"(b1));
}
__device__ __forceinline__ void cp16(uint32_t dst, const void* src) {
    asm volatile("cp.async.cg.shared.global [%0], [%1], 16;"
                 :: "r"(dst), "l"(src) : "memory");
}
__device__ __forceinline__ void cp16z(uint32_t dst, const void* src, int nbytes) {
    asm volatile("cp.async.ca.shared.global [%0], [%1], 16, %2;"
                 :: "r"(dst), "l"(src), "r"(nbytes) : "memory");
}
#define CP_COMMIT()  asm volatile("cp.async.commit_group;" ::: "memory")
#define CP_WAIT(N)   asm volatile("cp.async.wait_group %0;" :: "n"(N) : "memory")

__device__ __forceinline__ void sts_v2(uint32_t addr, float a, float b) {
    asm volatile("st.shared.v2.f32 [%0], {%1, %2};" :: "r"(addr), "f"(a), "f"(b));
}
__device__ __forceinline__ float4 lds_v4(uint32_t addr) {
    float4 v;
    asm volatile("ld.shared.v4.f32 {%0,%1,%2,%3}, [%4];"
                 : "=f"(v.x), "=f"(v.y), "=f"(v.z), "=f"(v.w) : "r"(addr));
    return v;
}

// ---------------------------------------------------------------------------
// kernel 1: fused prep — zero output+stats+barrier, feats->fp16, W^T->fp16
// ---------------------------------------------------------------------------
__global__ void prep_kernel(float* __restrict__ out,
                            const float* __restrict__ feats,
                            const float* __restrict__ W) {
    const size_t stride = (size_t)gridDim.x * blockDim.x;
    const size_t base = (size_t)blockIdx.x * blockDim.x + threadIdx.x;

    float4 z = make_float4(0.f, 0.f, 0.f, 0.f);
    for (size_t i = base; i < (size_t)N_OUT * (C / 4); i += stride)
        ((float4*)out)[i] = z;

    for (size_t i = base; i < (size_t)N_IN * (C / 4); i += stride) {
        float4 v = ((const float4*)feats)[i];
        __half h[4];
        h[0] = __float2half_rn(v.x);
        h[1] = __float2half_rn(v.y);
        h[2] = __float2half_rn(v.z);
        h[3] = __float2half_rn(v.w);
        ((uint2*)g_fh)[i] = *(uint2*)h;
    }

    for (size_t i = base; i < (size_t)K3 * C * C; i += stride) {
        int c  = (int)(i & (C - 1));
        int nn = (int)((i >> 7) & (C - 1));
        int k  = (int)(i >> 14);
        g_wt[i] = __float2half_rn(W[(size_t)k * C * C + (size_t)c * C + nn]);
    }

    if (blockIdx.x == 0 && threadIdx.x < C) {
        g_sum[threadIdx.x]   = 0.f;
        g_sumsq[threadIdx.x] = 0.f;
        if (threadIdx.x == 0) g_bar = 0u;     // reset grid barrier each replay
    }
}

// ---------------------------------------------------------------------------
// kernel 2: persistent pipelined gather -> HMMA -> staged row-contig scatter
// (byte-identical to the measured-best R6/R12 version)
// ---------------------------------------------------------------------------
#define PAD_C   136
#define SM_MAPS 0                                 // 3 slots x 1024 B
#define SM_B    3072                              // 34816 B
#define SM_A0   (SM_B + C * PAD_C * 2)            // 37888
#define SM_A1   (SM_A0 + TILE_M * PAD_C * 2)      // 72704
#define SM_TOT  (SM_A1 + TILE_M * PAD_C * 2)      // 107520

__global__ void __launch_bounds__(NTHR, 2)
scatter_gemm(const int* __restrict__ in_maps,
             const int* __restrict__ out_maps,
             float*     __restrict__ out) {
    extern __shared__ char smem[];
    const uint32_t smb = smem_u32(smem);
    const int tid  = threadIdx.x;
    const int wid  = tid >> 5;
    const int lane = tid & 31;

    const int start = blockIdx.x * TPB;
    const int end   = min(start + TPB, TASKS);
    if (start >= end) return;

    const int wm = (wid & 3) * 32;
    const int wn = (wid >> 2) * 64;
    const uint32_t aOff = ((uint32_t)(wm + (lane & 15)) * PAD_C + ((lane >> 4) << 3)) * 2;
    const uint32_t bOff = ((uint32_t)(wn + ((lane >> 4) << 3) + (lane & 7)) * PAD_C
                          + (((lane >> 3) & 1) << 3)) * 2;

    auto issue_maps = [&](int j) {
        if (tid < 64) {
            const int kq = j / NTILES, tq = j - kq * NTILES;
            const bool isOm = tid >= 32;
            const int c16 = tid & 31;
            const int* src = (isOm ? out_maps : in_maps)
                           + (size_t)kq * MP + (size_t)tq * TILE_M + c16 * 4;
            int nb = min(TILE_M, MP - tq * TILE_M) * 4 - c16 * 16;
            nb = nb < 0 ? 0 : (nb > 16 ? 16 : nb);
            cp16z(smb + SM_MAPS + (uint32_t)(j % 3) * 1024 + (isOm ? 512u : 0u)
                      + (uint32_t)c16 * 16, src, nb);
        }
    };
    auto issue_gather = [&](int j, uint32_t abase) {
        const int* imn = (const int*)(smem + SM_MAPS + (j % 3) * 1024);
#pragma unroll
        for (int it = 0; it < 2048 / NTHR; ++it) {
            int idx = it * NTHR + tid;
            int row = idx >> 4, c8 = idx & 15;
            cp16(abase + (uint32_t)(row * PAD_C + c8 * 8) * 2,
                 g_fh + (size_t)imn[row] * C + c8 * 8);
        }
    };

    issue_maps(start);
    CP_COMMIT();
    CP_WAIT(0);
    __syncthreads();
    issue_gather(start, smb + SM_A0);
    if (start + 1 < end) issue_maps(start + 1);
    CP_COMMIT();

    int cur_k = -1;

    for (int i = start; i < end; ++i) {
        const int k = i / NTILES;
        const int t = i - k * NTILES;
        const int buf = i & 1;

        CP_WAIT(0);
        __syncthreads();

        if (k != cur_k) {
            const uint4* bg = (const uint4*)(g_wt + (size_t)k * C * C);
#pragma unroll
            for (int it = 0; it < 2048 / NTHR; ++it) {
                int idx = it * NTHR + tid;
                int row = idx >> 4, c8 = idx & 15;
                *(uint4*)(smem + SM_B + (row * PAD_C + c8 * 8) * 2) = bg[idx];
            }
            cur_k = k;
            __syncthreads();
        }

        if (i + 1 < end) {
            issue_gather(i + 1, smb + (buf ? SM_A0 : SM_A1));
            if (i + 2 < end) issue_maps(i + 2);
            CP_COMMIT();
        }

        const uint32_t aAddr = smb + (buf ? SM_A1 : SM_A0) + aOff;
        const uint32_t bAddr = smb + SM_B + bOff;

        float acc[2][8][4];
#pragma unroll
        for (int mb = 0; mb < 2; ++mb)
#pragma unroll
            for (int nbt = 0; nbt < 8; ++nbt)
#pragma unroll
                for (int j = 0; j < 4; ++j) acc[mb][nbt][j] = 0.f;

#pragma unroll
        for (int ks = 0; ks < 8; ++ks) {
            const uint32_t kb = ks * 32;
            uint32_t a[2][4];
#pragma unroll
            for (int mb = 0; mb < 2; ++mb)
                ldsm_x4(a[mb][0], a[mb][1], a[mb][2], a[mb][3],
                        aAddr + mb * (16 * PAD_C * 2) + kb);
            uint32_t b[4][4];
#pragma unroll
            for (int g = 0; g < 4; ++g)
                ldsm_x4(b[g][0], b[g][1], b[g][2], b[g][3],
                        bAddr + g * (16 * PAD_C * 2) + kb);
#pragma unroll
            for (int mb = 0; mb < 2; ++mb)
#pragma unroll
                for (int g = 0; g < 4; ++g) {
                    mma16816(acc[mb][2 * g],     a[mb][0], a[mb][1], a[mb][2], a[mb][3],
                             b[g][0], b[g][1]);
                    mma16816(acc[mb][2 * g + 1], a[mb][0], a[mb][1], a[mb][2], a[mb][3],
                             b[g][2], b[g][3]);
                }
        }

        __syncthreads();

        const int* om = (const int*)(smem + SM_MAPS + (i % 3) * 1024) + 128;
        const int mvalid = min(TILE_M, MP - t * TILE_M);
        const uint32_t stage = smb + (buf ? SM_A1 : SM_A0) + (uint32_t)wid * 4096;

        const int rrA = lane >> 2;
        const int p   = lane & 3;
        const int jh  = p & 1;
        const int qr  = lane & 15;
        const int rhf = lane >> 4;

#pragma unroll
        for (int mb = 0; mb < 2; ++mb) {
#pragma unroll
            for (int nbt = 0; nbt < 8; ++nbt) {
                const int qi = nbt * 2 + (p >> 1);
                const uint32_t sw = (uint32_t)((qi ^ rrA) & 15);
                sts_v2(stage + (uint32_t)rrA * 256 + sw * 16 + (uint32_t)jh * 8,
                       acc[mb][nbt][0], acc[mb][nbt][1]);
                sts_v2(stage + (uint32_t)(rrA + 8) * 256 + sw * 16 + (uint32_t)jh * 8,
                       acc[mb][nbt][2], acc[mb][nbt][3]);
            }
            __syncwarp();
#pragma unroll
            for (int t8 = 0; t8 < 8; ++t8) {
                const int rr = t8 * 2 + rhf;
                float4 v = lds_v4(stage + (uint32_t)rr * 256
                                        + (uint32_t)((qr ^ (rr & 7)) & 15) * 16);
                const int grow = wm + mb * 16 + rr;
                if (grow < mvalid) {
                    float* dst = out + (size_t)om[grow] * C + wn + qr * 4;
                    red_v4(dst, v.x, v.y, v.z, v.w);
                }
            }
            __syncwarp();
        }
    }
}

// ---------------------------------------------------------------------------
// kernel 3: fused BN — forward stats, device grid barrier, reverse normalize
// grid MUST be GRID_BN (all CTAs co-resident: 4/SM x 148)
// ---------------------------------------------------------------------------
__global__ void __launch_bounds__(256, 4)
bn_fused(float* __restrict__ out,
         const float* __restrict__ gamma,
         const float* __restrict__ beta) {
    __shared__ float4 ssum[256];
    __shared__ float4 ssq[256];
    __shared__ float sc[C], sh[C];

    const int tid = threadIdx.x;
    const int c4  = tid & 31;
    const size_t n4 = (size_t)N_OUT * (C / 4);
    const size_t stride = (size_t)gridDim.x * blockDim.x;   // multiple of 32

    // ---- phase 1: forward stats (leaves tail of `out` resident in L2) ----
    float4 s = make_float4(0.f, 0.f, 0.f, 0.f);
    float4 q = make_float4(0.f, 0.f, 0.f, 0.f);
    const float4* o4 = (const float4*)out;
#pragma unroll 4
    for (size_t i = (size_t)blockIdx.x * blockDim.x + tid; i < n4; i += stride) {
        float4 v = o4[i];
        s.x += v.x; s.y += v.y; s.z += v.z; s.w += v.w;
        q.x += v.x * v.x; q.y += v.y * v.y; q.z += v.z * v.z; q.w += v.w * v.w;
    }
    ssum[tid] = s;
    ssq[tid]  = q;
    __syncthreads();
#pragma unroll
    for (int st = 128; st >= 32; st >>= 1) {
        if (tid < st) {
            ssum[tid].x += ssum[tid + st].x; ssum[tid].y += ssum[tid + st].y;
            ssum[tid].z += ssum[tid + st].z; ssum[tid].w += ssum[tid + st].w;
            ssq[tid].x  += ssq[tid + st].x;  ssq[tid].y  += ssq[tid + st].y;
            ssq[tid].z  += ssq[tid + st].z;  ssq[tid].w  += ssq[tid + st].w;
        }
        __syncthreads();
    }
    if (tid < 32) {
        atomicAdd(&g_sum[c4 * 4 + 0], ssum[tid].x);
        atomicAdd(&g_sum[c4 * 4 + 1], ssum[tid].y);
        atomicAdd(&g_sum[c4 * 4 + 2], ssum[tid].z);
        atomicAdd(&g_sum[c4 * 4 + 3], ssum[tid].w);
        atomicAdd(&g_sumsq[c4 * 4 + 0], ssq[tid].x);
        atomicAdd(&g_sumsq[c4 * 4 + 1], ssq[tid].y);
        atomicAdd(&g_sumsq[c4 * 4 + 2], ssq[tid].z);
        atomicAdd(&g_sumsq[c4 * 4 + 3], ssq[tid].w);
    }

    // ---- device grid barrier (all GRID_BN CTAs are co-resident) ----
    __syncthreads();
    if (tid == 0) {
        __threadfence();                        // publish atomics
        atomicAdd(&g_bar, 1u);
        while (atomicAdd(&g_bar, 0u) < (unsigned)gridDim.x) { }
        __threadfence();                        // acquire g_sum/g_sumsq
    }
    __syncthreads();

    // ---- fold stats into per-channel scale/shift ----
    if (tid < C) {
        const float inv_n = 1.0f / (float)N_OUT;
        float mean = g_sum[tid] * inv_n;
        float var  = g_sumsq[tid] * inv_n - mean * mean;
        float scv  = rsqrtf(var + EPS) * gamma[tid];
        sc[tid] = scv;
        sh[tid] = beta[tid] - mean * scv;
    }
    __syncthreads();

    // ---- phase 2: reverse normalize (hits L2-resident tail first) ----
    for (size_t j = (size_t)blockIdx.x * blockDim.x + tid; j < n4; j += stride) {
        const size_t i = n4 - 1 - j;
        int cc = (int)(i & 31);
        float4 v = ((float4*)out)[i];
        float4 ss = *(float4*)(sc + cc * 4);
        float4 hh = *(float4*)(sh + cc * 4);
        v.x = v.x * ss.x + hh.x;
        v.y = v.y * ss.y + hh.y;
        v.z = v.z * ss.z + hh.z;
        v.w = v.w * ss.w + hh.w;
        ((float4*)out)[i] = v;
    }
}

// ---------------------------------------------------------------------------
// launch
// ---------------------------------------------------------------------------
extern "C" void kernel_launch(void* const* d_in, const int* in_sizes, int n_in,
                              void* d_out, int out_size) {
    const float* feats    = (const float*)d_in[0];
    const float* W        = (const float*)d_in[1];
    const float* gamma    = (const float*)d_in[2];
    const float* beta     = (const float*)d_in[3];
    const int*   in_maps  = (const int*)d_in[4];
    const int*   out_maps = (const int*)d_in[5];
    float* out = (float*)d_out;

    cudaFuncSetAttribute(scatter_gemm,
                         cudaFuncAttributeMaxDynamicSharedMemorySize, SM_TOT);

    prep_kernel<<<1184, 256>>>(out, feats, W);
    scatter_gemm<<<GRID_MAIN, NTHR, SM_TOT>>>(in_maps, out_maps, out);
    bn_fused<<<GRID_BN, 256>>>(out, gamma, beta);
}